// round 12
// baseline (speedup 1.0000x reference)
#include <cuda_runtime.h>
#include <cuda_fp16.h>
#include <cstdint>

#define N_NODES  100000
#define N_EDGES  1600000
#define IN_CH    128
#define HID      128
#define OUT_CH   64
#define N_GRAPHS 512

#define CHUNK0   50176                      // 392 * 128
#define CHUNK1   (N_NODES - CHUNK0)         // 49824

static const int NB_SCAN = (N_NODES + 1023) / 1024;   // 98

// ---------------- scratch (device globals) ----------------------------------
__device__ int    g_deg[N_NODES];
__device__ int    g_incl[N_NODES];
__device__ int    g_bsum[128];
__device__ int    g_rowptr[N_NODES + 1];
__device__ int    g_rank[N_EDGES];
__device__ int    g_srcidx[N_EDGES];
__device__ float  g_dinv[N_NODES];
__device__ __half g_hs [(size_t)N_NODES * HID];    // fp16 dinv*(X@W1) — conv1 gather src
__device__ __half g_hs2[(size_t)N_NODES * HID];    // fp16 dinv*(h2@W2) — conv2 gather src
__device__ __half g_h2 [(size_t)N_NODES * HID];    // fp16 conv output

// ---------------- side stream / events (static init: in memory baseline) ----
struct ForkRes {
    cudaStream_t s2;
    cudaEvent_t  evO, evC, evG1, evA1a, evA1b, evG2a, evG2b;
    ForkRes() {
        cudaStreamCreateWithFlags(&s2, cudaStreamNonBlocking);
        cudaEventCreateWithFlags(&evO,   cudaEventDisableTiming);
        cudaEventCreateWithFlags(&evC,   cudaEventDisableTiming);
        cudaEventCreateWithFlags(&evG1,  cudaEventDisableTiming);
        cudaEventCreateWithFlags(&evA1a, cudaEventDisableTiming);
        cudaEventCreateWithFlags(&evA1b, cudaEventDisableTiming);
        cudaEventCreateWithFlags(&evG2a, cudaEventDisableTiming);
        cudaEventCreateWithFlags(&evG2b, cudaEventDisableTiming);
    }
};
static ForkRes g_fork;

__device__ __half g_Wt1[HID * HID];
__device__ __half g_Wt2[HID * HID];

// ---------------- CSR build --------------------------------------------------
__global__ void k_count(const int* __restrict__ ei) {
    int t = blockIdx.x * blockDim.x + threadIdx.x;
    if (t * 4 >= N_EDGES) return;
    int4 d = ((const int4*)(ei + N_EDGES))[t];
    int4 r;
    r.x = atomicAdd(&g_deg[d.x], 1);
    r.y = atomicAdd(&g_deg[d.y], 1);
    r.z = atomicAdd(&g_deg[d.z], 1);
    r.w = atomicAdd(&g_deg[d.w], 1);
    ((int4*)g_rank)[t] = r;
}

__global__ void k_scan1() {
    __shared__ int s[1024];
    int t = threadIdx.x;
    int i = blockIdx.x * 1024 + t;
    int v = (i < N_NODES) ? g_deg[i] : 0;
    s[t] = v;
    __syncthreads();
    for (int off = 1; off < 1024; off <<= 1) {
        int a = (t >= off) ? s[t - off] : 0;
        __syncthreads();
        s[t] += a;
        __syncthreads();
    }
    if (i < N_NODES) g_incl[i] = s[t];
    if (t == 1023) g_bsum[blockIdx.x] = s[1023];
}

__global__ void k_scan3(int nb) {
    __shared__ int tmp[128];
    __shared__ int soff;
    int t = threadIdx.x;
    if (t < 128) tmp[t] = (t < (int)blockIdx.x && t < nb) ? g_bsum[t] : 0;
    __syncthreads();
    if (t == 0) {
        int s = 0;
#pragma unroll
        for (int j = 0; j < 128; j++) s += tmp[j];
        soff = s;
    }
    __syncthreads();
    int i = blockIdx.x * 1024 + t;
    if (i < N_NODES) {
        int d = g_deg[i];
        g_rowptr[i] = g_incl[i] - d + soff;
        g_dinv[i]   = rsqrtf((float)(d + 1));
    }
    if (i == 0) g_rowptr[N_NODES] = N_EDGES;
}

__global__ void k_scatter(const int* __restrict__ ei) {
    int t = blockIdx.x * blockDim.x + threadIdx.x;
    if (t * 4 >= N_EDGES) return;
    int4 s = ((const int4*)ei)[t];
    int4 d = ((const int4*)(ei + N_EDGES))[t];
    int4 r = ((const int4*)g_rank)[t];
    g_srcidx[g_rowptr[d.x] + r.x] = s.x;
    g_srcidx[g_rowptr[d.y] + r.y] = s.y;
    g_srcidx[g_rowptr[d.z] + r.z] = s.z;
    g_srcidx[g_rowptr[d.w] + r.w] = s.w;
}

// ---------------- W transpose to fp16 ----------------------------------------
__global__ void k_wt(const float* __restrict__ W, __half* __restrict__ Wt) {
    __shared__ float tile[32][33];
    int bx = blockIdx.x, by = blockIdx.y;
    int tx = threadIdx.x, ty = threadIdx.y;
    int k = by * 32 + ty, n = bx * 32 + tx;
    tile[ty][tx] = W[k * HID + n];
    __syncthreads();
    int on = bx * 32 + ty, ok = by * 32 + tx;
    Wt[on * HID + ok] = __float2half_rn(tile[tx][ty]);
}

// ---------------- tensor-core GEMM (128x128 W, K=128) -----------------------
// out[row] = fp16( rsqrtf(deg[row]+1) * (X[row] @ W) ). Rows [rowOff, rowEnd).
template <bool HALF_IN>
__global__ void __launch_bounds__(256) k_gemm_mma(
        const void* __restrict__ Xv, const __half* __restrict__ Wt,
        __half* __restrict__ out, int rowOff, int rowEnd) {
    constexpr int NT = 16;
    constexpr int AS = 136;
    extern __shared__ __half sm[];
    __half* Asm = sm;
    __half* Bt  = sm + 128 * AS;
    int t = threadIdx.x;
    int rowBase = rowOff + blockIdx.x * 128;

    if (HALF_IN) {
        const uint4* X = (const uint4*)Xv;
        for (int idx = t; idx < 128 * 16; idx += 256) {
            int r = idx >> 4, c8 = idx & 15;
            uint4 v = make_uint4(0u, 0u, 0u, 0u);
            int gr = rowBase + r;
            if (gr < rowEnd) v = X[(size_t)gr * 16 + c8];
            *(uint4*)&Asm[r * AS + c8 * 8] = v;
        }
    } else {
        const float4* X = (const float4*)Xv;
        for (int idx = t; idx < 128 * 32; idx += 256) {
            int r = idx >> 5, c4 = idx & 31;
            float4 v = make_float4(0.f, 0.f, 0.f, 0.f);
            int gr = rowBase + r;
            if (gr < rowEnd) v = X[(size_t)gr * 32 + c4];
            *(__half2*)&Asm[r * AS + c4 * 4]     = __floats2half2_rn(v.x, v.y);
            *(__half2*)&Asm[r * AS + c4 * 4 + 2] = __floats2half2_rn(v.z, v.w);
        }
    }
    {
        const uint4* Wt4 = (const uint4*)Wt;
        for (int idx = t; idx < 128 * 16; idx += 256) {
            int n = idx >> 4, c8 = idx & 15;
            *(uint4*)&Bt[n * AS + c8 * 8] = Wt4[idx];
        }
    }
    __syncthreads();

    int w = t >> 5, lane = t & 31;
    int g = lane >> 2, s = lane & 3;
    int strip = w * 16;

    float acc[NT][4];
#pragma unroll
    for (int nt = 0; nt < NT; nt++)
#pragma unroll
        for (int q = 0; q < 4; q++) acc[nt][q] = 0.f;

    const __half* Arow0 = &Asm[(strip + g) * AS + s * 2];
    const __half* Arow1 = Arow0 + 8 * AS;
#pragma unroll
    for (int ks = 0; ks < 8; ks++) {
        int kb = ks * 16;
        unsigned a0 = *(const unsigned*)(Arow0 + kb);
        unsigned a1 = *(const unsigned*)(Arow1 + kb);
        unsigned a2 = *(const unsigned*)(Arow0 + kb + 8);
        unsigned a3 = *(const unsigned*)(Arow1 + kb + 8);
#pragma unroll
        for (int nt = 0; nt < NT; nt++) {
            const __half* Bp = &Bt[(nt * 8 + g) * AS + kb + s * 2];
            unsigned b0 = *(const unsigned*)(Bp);
            unsigned b1 = *(const unsigned*)(Bp + 8);
            asm volatile(
                "mma.sync.aligned.m16n8k16.row.col.f32.f16.f16.f32 "
                "{%0,%1,%2,%3}, {%4,%5,%6,%7}, {%8,%9}, {%0,%1,%2,%3};"
                : "+f"(acc[nt][0]), "+f"(acc[nt][1]), "+f"(acc[nt][2]), "+f"(acc[nt][3])
                : "r"(a0), "r"(a1), "r"(a2), "r"(a3), "r"(b0), "r"(b1));
        }
    }

    int gr0 = rowBase + strip + g;
    int gr1 = gr0 + 8;
    float dv0 = (gr0 < rowEnd) ? rsqrtf((float)(g_deg[gr0] + 1)) : 0.f;
    float dv1 = (gr1 < rowEnd) ? rsqrtf((float)(g_deg[gr1] + 1)) : 0.f;
#pragma unroll
    for (int nt = 0; nt < NT; nt++) {
        int col = nt * 8 + s * 2;
        if (gr0 < rowEnd)
            *(__half2*)&out[(size_t)gr0 * HID + col] =
                __floats2half2_rn(acc[nt][0] * dv0, acc[nt][1] * dv0);
        if (gr1 < rowEnd)
            *(__half2*)&out[(size_t)gr1 * HID + col] =
                __floats2half2_rn(acc[nt][2] * dv1, acc[nt][3] * dv1);
    }
}

// ---------------- aggregation, node range [off, end) ------------------------
__device__ __forceinline__ void acc8(float* a, uint4 u) {
    const __half2* h = (const __half2*)&u;
#pragma unroll
    for (int j = 0; j < 4; j++) {
        float2 f = __half22float2(h[j]);
        a[2 * j]     += f.x;
        a[2 * j + 1] += f.y;
    }
}

__global__ void __launch_bounds__(256) k_agg(
        const uint4* __restrict__ hs, const float* __restrict__ bias,
        uint4* __restrict__ out, int off, int end) {
    int warp = off + ((blockIdx.x * blockDim.x + threadIdx.x) >> 5);
    int lane = threadIdx.x & 31;
    if (warp >= end) return;
    int hw = lane >> 4, c = lane & 15;

    float a[8] = {0.f, 0.f, 0.f, 0.f, 0.f, 0.f, 0.f, 0.f};
    if (hw == 0) acc8(a, hs[(size_t)warp * 16 + c]);   // self loop

    int s0 = g_rowptr[warp];
    int s1 = g_rowptr[warp + 1];
    int i = s0 + hw;
    for (; i + 14 < s1; i += 16) {
        int e[8];
#pragma unroll
        for (int q = 0; q < 8; q++) e[q] = g_srcidx[i + 2 * q];
        uint4 v[8];
#pragma unroll
        for (int q = 0; q < 8; q++) v[q] = hs[(size_t)e[q] * 16 + c];
#pragma unroll
        for (int q = 0; q < 8; q++) acc8(a, v[q]);
    }
    for (; i + 6 < s1; i += 8) {
        int e0 = g_srcidx[i];
        int e1 = g_srcidx[i + 2];
        int e2 = g_srcidx[i + 4];
        int e3 = g_srcidx[i + 6];
        uint4 v0 = hs[(size_t)e0 * 16 + c];
        uint4 v1 = hs[(size_t)e1 * 16 + c];
        uint4 v2 = hs[(size_t)e2 * 16 + c];
        uint4 v3 = hs[(size_t)e3 * 16 + c];
        acc8(a, v0); acc8(a, v1); acc8(a, v2); acc8(a, v3);
    }
    for (; i < s1; i += 2) acc8(a, hs[(size_t)g_srcidx[i] * 16 + c]);

#pragma unroll
    for (int q = 0; q < 8; q++) a[q] += __shfl_down_sync(0xffffffffu, a[q], 16);

    if (hw == 0) {
        float dv = g_dinv[warp];
        float4 b0 = ((const float4*)bias)[2 * c];
        float4 b1 = ((const float4*)bias)[2 * c + 1];
        __half2 h0 = __floats2half2_rn(fmaxf(fmaf(dv, a[0], b0.x), 0.f),
                                       fmaxf(fmaf(dv, a[1], b0.y), 0.f));
        __half2 h1 = __floats2half2_rn(fmaxf(fmaf(dv, a[2], b0.z), 0.f),
                                       fmaxf(fmaf(dv, a[3], b0.w), 0.f));
        __half2 h2 = __floats2half2_rn(fmaxf(fmaf(dv, a[4], b1.x), 0.f),
                                       fmaxf(fmaf(dv, a[5], b1.y), 0.f));
        __half2 h3 = __floats2half2_rn(fmaxf(fmaf(dv, a[6], b1.z), 0.f),
                                       fmaxf(fmaf(dv, a[7], b1.w), 0.f));
        uint4 o;
        o.x = *(unsigned*)&h0; o.y = *(unsigned*)&h1;
        o.z = *(unsigned*)&h2; o.w = *(unsigned*)&h3;
        out[(size_t)warp * 16 + c] = o;
    }
}

// ---------------- fused pool + MLP head (fp32 math, exact) ------------------
__global__ void __launch_bounds__(128) k_head(
        const __half* __restrict__ h, const int* __restrict__ batch,
        const float* __restrict__ W3, const float* __restrict__ b3,
        const float* __restrict__ W4, const float* __restrict__ b4,
        float* __restrict__ out) {
    __shared__ float sp[128];
    __shared__ float sm2[128];
    int g = blockIdx.x;
    int c = threadIdx.x;

    int lo = 0, hi = N_NODES;
    while (lo < hi) { int mid = (lo + hi) >> 1; if (batch[mid] < g) lo = mid + 1; else hi = mid; }
    int start = lo;
    lo = start; hi = N_NODES;
    while (lo < hi) { int mid = (lo + hi) >> 1; if (batch[mid] < g + 1) lo = mid + 1; else hi = mid; }
    int end = lo;

    float acc = 0.f;
    for (int r = start; r < end; r++) acc += __half2float(h[(size_t)r * HID + c]);
    int cnt = end - start;
    sp[c] = acc / (float)(cnt > 0 ? cnt : 1);
    __syncthreads();

    float m = 0.f;
#pragma unroll 8
    for (int k = 0; k < HID; k++) m = fmaf(sp[k], W3[k * HID + c], m);
    sm2[c] = fmaxf(m + b3[c], 0.f);
    __syncthreads();

    if (c < OUT_CH) {
        float o = 0.f;
#pragma unroll 8
        for (int k = 0; k < HID; k++) o = fmaf(sm2[k], W4[k * OUT_CH + c], o);
        out[g * OUT_CH + c] = o + b4[c];
    }
}

// ---------------- launch ------------------------------------------------------
extern "C" void kernel_launch(void* const* d_in, const int* in_sizes, int n_in,
                              void* d_out, int out_size) {
    const float* x   = (const float*)d_in[0];
    const int*   ei  = (const int*)d_in[1];
    const int*   bat = (const int*)d_in[2];
    const float* W1  = (const float*)d_in[3];
    const float* b1  = (const float*)d_in[4];
    const float* W2  = (const float*)d_in[5];
    const float* b2  = (const float*)d_in[6];
    const float* W3  = (const float*)d_in[7];
    const float* b3  = (const float*)d_in[8];
    const float* W4  = (const float*)d_in[9];
    const float* b4  = (const float*)d_in[10];
    float* out = (float*)d_out;

    __half* hs; __half* hs2; __half* h2; int* deg; __half* wt1; __half* wt2;
    cudaGetSymbolAddress((void**)&hs,  g_hs);
    cudaGetSymbolAddress((void**)&hs2, g_hs2);
    cudaGetSymbolAddress((void**)&h2,  g_h2);
    cudaGetSymbolAddress((void**)&deg, g_deg);
    cudaGetSymbolAddress((void**)&wt1, g_Wt1);
    cudaGetSymbolAddress((void**)&wt2, g_Wt2);

    const int SMG = 2 * 128 * 136 * 2;   // 69632 B
    cudaFuncSetAttribute(k_gemm_mma<false>, cudaFuncAttributeMaxDynamicSharedMemorySize, SMG);
    cudaFuncSetAttribute(k_gemm_mma<true>,  cudaFuncAttributeMaxDynamicSharedMemorySize, SMG);

    const int TB = 256;
    int nbE4 = (N_EDGES / 4 + TB - 1) / TB;
    int nbGemmAll = (N_NODES + 127) / 128;     // 782
    int nbGemmC0  = CHUNK0 / 128;              // 392
    int nbGemmC1  = (CHUNK1 + 127) / 128;      // 390
    int nbAggC0   = (CHUNK0 * 32 + TB - 1) / TB;
    int nbAggC1   = (CHUNK1 * 32 + TB - 1) / TB;

    cudaStream_t s2 = g_fork.s2;

    // fork at origin: W transposes are fully independent
    cudaEventRecord(g_fork.evO, 0);
    cudaStreamWaitEvent(s2, g_fork.evO, 0);
    k_wt<<<dim3(4, 4), dim3(32, 32), 0, s2>>>(W1, wt1);
    k_wt<<<dim3(4, 4), dim3(32, 32), 0, s2>>>(W2, wt2);

    // main: deg + ranks (concurrent with W transposes)
    cudaMemsetAsync(deg, 0, N_NODES * sizeof(int));
    k_count<<<nbE4, TB>>>(ei);
    cudaEventRecord(g_fork.evC, 0);

    // side: GEMM1 (epilogue scales by rsqrt(deg+1)) while main scans+scatters
    cudaStreamWaitEvent(s2, g_fork.evC, 0);
    k_gemm_mma<false><<<nbGemmAll, 256, SMG, s2>>>(x, wt1, hs, 0, N_NODES);
    cudaEventRecord(g_fork.evG1, s2);

    k_scan1<<<NB_SCAN, 1024>>>();
    k_scan3<<<NB_SCAN, 1024>>>(NB_SCAN);
    k_scatter<<<nbE4, TB>>>(ei);

    // join GEMM1; pipeline agg1 chunks (hs -> h2) against gemm2 (h2 -> hs2).
    // Race-free: gemm2 writes hs2, never hs, so concurrent agg1_b reads of hs
    // are safe; gemm2_a reads h2[0:C0] which agg1_a fully wrote.
    cudaStreamWaitEvent(0, g_fork.evG1, 0);

    k_agg<<<nbAggC0, TB>>>((const uint4*)hs, b1, (uint4*)h2, 0, CHUNK0);
    cudaEventRecord(g_fork.evA1a, 0);
    cudaStreamWaitEvent(s2, g_fork.evA1a, 0);
    k_gemm_mma<true><<<nbGemmC0, 256, SMG, s2>>>(h2, wt2, hs2, 0, CHUNK0);
    cudaEventRecord(g_fork.evG2a, s2);

    k_agg<<<nbAggC1, TB>>>((const uint4*)hs, b1, (uint4*)h2, CHUNK0, N_NODES);
    cudaEventRecord(g_fork.evA1b, 0);
    cudaStreamWaitEvent(s2, g_fork.evA1b, 0);
    k_gemm_mma<true><<<nbGemmC1, 256, SMG, s2>>>(h2, wt2, hs2, CHUNK0, N_NODES);
    cudaEventRecord(g_fork.evG2b, s2);

    cudaStreamWaitEvent(0, g_fork.evG2a, 0);
    cudaStreamWaitEvent(0, g_fork.evG2b, 0);

    // conv2 aggregation (global gather from hs2) + head
    k_agg<<<(N_NODES * 32 + TB - 1) / TB, TB>>>((const uint4*)hs2, b2, (uint4*)h2, 0, N_NODES);
    k_head<<<N_GRAPHS, 128>>>(h2, bat, W3, b3, W4, b4, out);
}

// round 13
// speedup vs baseline: 1.0946x; 1.0946x over previous
#include <cuda_runtime.h>
#include <cuda_fp16.h>
#include <cstdint>

#define N_NODES  100000
#define N_EDGES  1600000
#define IN_CH    128
#define HID      128
#define OUT_CH   64
#define N_GRAPHS 512

static const int NB_SCAN = (N_NODES + 1023) / 1024;   // 98

// ---------------- scratch (device globals) ----------------------------------
__device__ int    g_deg[N_NODES];
__device__ int    g_incl[N_NODES];
__device__ int    g_bsum[128];
__device__ int    g_rowptr[N_NODES + 1];
__device__ int    g_rank[N_EDGES];
__device__ int    g_srcidx[N_EDGES];
__device__ float  g_dinv[N_NODES];
__device__ __half g_hs[(size_t)N_NODES * HID];     // fp16 dinv*(X@W)
__device__ __half g_h2[(size_t)N_NODES * HID];     // fp16 conv output
__device__ __half g_Wt1[HID * HID];
__device__ __half g_Wt2[HID * HID];

// ---------------- side stream / events (static init: in memory baseline) ----
struct ForkRes {
    cudaStream_t s2;
    cudaEvent_t  evO, evC, evG1;
    ForkRes() {
        cudaStreamCreateWithFlags(&s2, cudaStreamNonBlocking);
        cudaEventCreateWithFlags(&evO,  cudaEventDisableTiming);
        cudaEventCreateWithFlags(&evC,  cudaEventDisableTiming);
        cudaEventCreateWithFlags(&evG1, cudaEventDisableTiming);
    }
};
static ForkRes g_fork;

// ---------------- CSR build --------------------------------------------------
__global__ void k_count(const int* __restrict__ ei) {
    int t = blockIdx.x * blockDim.x + threadIdx.x;
    if (t * 4 >= N_EDGES) return;
    int4 d = ((const int4*)(ei + N_EDGES))[t];
    int4 r;
    r.x = atomicAdd(&g_deg[d.x], 1);
    r.y = atomicAdd(&g_deg[d.y], 1);
    r.z = atomicAdd(&g_deg[d.z], 1);
    r.w = atomicAdd(&g_deg[d.w], 1);
    ((int4*)g_rank)[t] = r;
}

__global__ void k_scan1() {
    __shared__ int s[1024];
    int t = threadIdx.x;
    int i = blockIdx.x * 1024 + t;
    int v = (i < N_NODES) ? g_deg[i] : 0;
    s[t] = v;
    __syncthreads();
    for (int off = 1; off < 1024; off <<= 1) {
        int a = (t >= off) ? s[t - off] : 0;
        __syncthreads();
        s[t] += a;
        __syncthreads();
    }
    if (i < N_NODES) g_incl[i] = s[t];
    if (t == 1023) g_bsum[blockIdx.x] = s[1023];
}

__global__ void k_scan3(int nb) {
    __shared__ int tmp[128];
    __shared__ int soff;
    int t = threadIdx.x;
    if (t < 128) tmp[t] = (t < (int)blockIdx.x && t < nb) ? g_bsum[t] : 0;
    __syncthreads();
    if (t == 0) {
        int s = 0;
#pragma unroll
        for (int j = 0; j < 128; j++) s += tmp[j];
        soff = s;
    }
    __syncthreads();
    int i = blockIdx.x * 1024 + t;
    if (i < N_NODES) {
        int d = g_deg[i];
        g_rowptr[i] = g_incl[i] - d + soff;
        g_dinv[i]   = rsqrtf((float)(d + 1));
    }
    if (i == 0) g_rowptr[N_NODES] = N_EDGES;
}

__global__ void k_scatter(const int* __restrict__ ei) {
    int t = blockIdx.x * blockDim.x + threadIdx.x;
    if (t * 4 >= N_EDGES) return;
    int4 s = ((const int4*)ei)[t];
    int4 d = ((const int4*)(ei + N_EDGES))[t];
    int4 r = ((const int4*)g_rank)[t];
    g_srcidx[g_rowptr[d.x] + r.x] = s.x;
    g_srcidx[g_rowptr[d.y] + r.y] = s.y;
    g_srcidx[g_rowptr[d.z] + r.z] = s.z;
    g_srcidx[g_rowptr[d.w] + r.w] = s.w;
}

// ---------------- W transpose to fp16 ----------------------------------------
__global__ void k_wt(const float* __restrict__ W, __half* __restrict__ Wt) {
    __shared__ float tile[32][33];
    int bx = blockIdx.x, by = blockIdx.y;
    int tx = threadIdx.x, ty = threadIdx.y;
    int k = by * 32 + ty, n = bx * 32 + tx;
    tile[ty][tx] = W[k * HID + n];
    __syncthreads();
    int on = bx * 32 + ty, ok = by * 32 + tx;
    Wt[on * HID + ok] = __float2half_rn(tile[tx][ty]);
}

// ---------------- tensor-core GEMM (128x128 W, K=128) -----------------------
// out[row] = fp16( rsqrtf(deg[row]+1) * (X[row] @ W) )
template <bool HALF_IN>
__global__ void __launch_bounds__(256) k_gemm_mma(
        const void* __restrict__ Xv, const __half* __restrict__ Wt,
        __half* __restrict__ out, int M) {
    constexpr int NT = 16;
    constexpr int AS = 136;
    extern __shared__ __half sm[];
    __half* Asm = sm;
    __half* Bt  = sm + 128 * AS;
    int t = threadIdx.x;
    int rowBase = blockIdx.x * 128;

    if (HALF_IN) {
        const uint4* X = (const uint4*)Xv;
        for (int idx = t; idx < 128 * 16; idx += 256) {
            int r = idx >> 4, c8 = idx & 15;
            uint4 v = make_uint4(0u, 0u, 0u, 0u);
            int gr = rowBase + r;
            if (gr < M) v = X[(size_t)gr * 16 + c8];
            *(uint4*)&Asm[r * AS + c8 * 8] = v;
        }
    } else {
        const float4* X = (const float4*)Xv;
        for (int idx = t; idx < 128 * 32; idx += 256) {
            int r = idx >> 5, c4 = idx & 31;
            float4 v = make_float4(0.f, 0.f, 0.f, 0.f);
            int gr = rowBase + r;
            if (gr < M) v = X[(size_t)gr * 32 + c4];
            *(__half2*)&Asm[r * AS + c4 * 4]     = __floats2half2_rn(v.x, v.y);
            *(__half2*)&Asm[r * AS + c4 * 4 + 2] = __floats2half2_rn(v.z, v.w);
        }
    }
    {
        const uint4* Wt4 = (const uint4*)Wt;
        for (int idx = t; idx < 128 * 16; idx += 256) {
            int n = idx >> 4, c8 = idx & 15;
            *(uint4*)&Bt[n * AS + c8 * 8] = Wt4[idx];
        }
    }
    __syncthreads();

    int w = t >> 5, lane = t & 31;
    int g = lane >> 2, s = lane & 3;
    int strip = w * 16;

    float acc[NT][4];
#pragma unroll
    for (int nt = 0; nt < NT; nt++)
#pragma unroll
        for (int q = 0; q < 4; q++) acc[nt][q] = 0.f;

    const __half* Arow0 = &Asm[(strip + g) * AS + s * 2];
    const __half* Arow1 = Arow0 + 8 * AS;
#pragma unroll
    for (int ks = 0; ks < 8; ks++) {
        int kb = ks * 16;
        unsigned a0 = *(const unsigned*)(Arow0 + kb);
        unsigned a1 = *(const unsigned*)(Arow1 + kb);
        unsigned a2 = *(const unsigned*)(Arow0 + kb + 8);
        unsigned a3 = *(const unsigned*)(Arow1 + kb + 8);
#pragma unroll
        for (int nt = 0; nt < NT; nt++) {
            const __half* Bp = &Bt[(nt * 8 + g) * AS + kb + s * 2];
            unsigned b0 = *(const unsigned*)(Bp);
            unsigned b1 = *(const unsigned*)(Bp + 8);
            asm volatile(
                "mma.sync.aligned.m16n8k16.row.col.f32.f16.f16.f32 "
                "{%0,%1,%2,%3}, {%4,%5,%6,%7}, {%8,%9}, {%0,%1,%2,%3};"
                : "+f"(acc[nt][0]), "+f"(acc[nt][1]), "+f"(acc[nt][2]), "+f"(acc[nt][3])
                : "r"(a0), "r"(a1), "r"(a2), "r"(a3), "r"(b0), "r"(b1));
        }
    }

    int gr0 = rowBase + strip + g;
    int gr1 = gr0 + 8;
    float dv0 = (gr0 < M) ? rsqrtf((float)(g_deg[gr0] + 1)) : 0.f;
    float dv1 = (gr1 < M) ? rsqrtf((float)(g_deg[gr1] + 1)) : 0.f;
#pragma unroll
    for (int nt = 0; nt < NT; nt++) {
        int col = nt * 8 + s * 2;
        if (gr0 < M)
            *(__half2*)&out[(size_t)gr0 * HID + col] =
                __floats2half2_rn(acc[nt][0] * dv0, acc[nt][1] * dv0);
        if (gr1 < M)
            *(__half2*)&out[(size_t)gr1 * HID + col] =
                __floats2half2_rn(acc[nt][2] * dv1, acc[nt][3] * dv1);
    }
}

// ---------------- aggregation: warp per node, 2 half-warps, LDG.128 ---------
__device__ __forceinline__ void acc8(float* a, uint4 u) {
    const __half2* h = (const __half2*)&u;
#pragma unroll
    for (int j = 0; j < 4; j++) {
        float2 f = __half22float2(h[j]);
        a[2 * j]     += f.x;
        a[2 * j + 1] += f.y;
    }
}

__global__ void __launch_bounds__(256) k_agg(
        const uint4* __restrict__ hs, const float* __restrict__ bias,
        uint4* __restrict__ out) {
    int warp = (blockIdx.x * blockDim.x + threadIdx.x) >> 5;
    int lane = threadIdx.x & 31;
    if (warp >= N_NODES) return;
    int hw = lane >> 4, c = lane & 15;

    float a[8] = {0.f, 0.f, 0.f, 0.f, 0.f, 0.f, 0.f, 0.f};
    if (hw == 0) acc8(a, hs[(size_t)warp * 16 + c]);   // self loop

    int s0 = g_rowptr[warp];
    int s1 = g_rowptr[warp + 1];
    int i = s0 + hw;
    for (; i + 14 < s1; i += 16) {
        int e[8];
#pragma unroll
        for (int q = 0; q < 8; q++) e[q] = g_srcidx[i + 2 * q];
        uint4 v[8];
#pragma unroll
        for (int q = 0; q < 8; q++) v[q] = hs[(size_t)e[q] * 16 + c];
#pragma unroll
        for (int q = 0; q < 8; q++) acc8(a, v[q]);
    }
    for (; i + 6 < s1; i += 8) {
        int e0 = g_srcidx[i];
        int e1 = g_srcidx[i + 2];
        int e2 = g_srcidx[i + 4];
        int e3 = g_srcidx[i + 6];
        uint4 v0 = hs[(size_t)e0 * 16 + c];
        uint4 v1 = hs[(size_t)e1 * 16 + c];
        uint4 v2 = hs[(size_t)e2 * 16 + c];
        uint4 v3 = hs[(size_t)e3 * 16 + c];
        acc8(a, v0); acc8(a, v1); acc8(a, v2); acc8(a, v3);
    }
    for (; i < s1; i += 2) acc8(a, hs[(size_t)g_srcidx[i] * 16 + c]);

#pragma unroll
    for (int q = 0; q < 8; q++) a[q] += __shfl_down_sync(0xffffffffu, a[q], 16);

    if (hw == 0) {
        float dv = g_dinv[warp];
        float4 b0 = ((const float4*)bias)[2 * c];
        float4 b1 = ((const float4*)bias)[2 * c + 1];
        __half2 h0 = __floats2half2_rn(fmaxf(fmaf(dv, a[0], b0.x), 0.f),
                                       fmaxf(fmaf(dv, a[1], b0.y), 0.f));
        __half2 h1 = __floats2half2_rn(fmaxf(fmaf(dv, a[2], b0.z), 0.f),
                                       fmaxf(fmaf(dv, a[3], b0.w), 0.f));
        __half2 h2 = __floats2half2_rn(fmaxf(fmaf(dv, a[4], b1.x), 0.f),
                                       fmaxf(fmaf(dv, a[5], b1.y), 0.f));
        __half2 h3 = __floats2half2_rn(fmaxf(fmaf(dv, a[6], b1.z), 0.f),
                                       fmaxf(fmaf(dv, a[7], b1.w), 0.f));
        uint4 o;
        o.x = *(unsigned*)&h0; o.y = *(unsigned*)&h1;
        o.z = *(unsigned*)&h2; o.w = *(unsigned*)&h3;
        out[(size_t)warp * 16 + c] = o;
    }
}

// ---------------- fused pool + MLP head (fp32 math, exact) ------------------
__global__ void __launch_bounds__(128) k_head(
        const __half* __restrict__ h, const int* __restrict__ batch,
        const float* __restrict__ W3, const float* __restrict__ b3,
        const float* __restrict__ W4, const float* __restrict__ b4,
        float* __restrict__ out) {
    __shared__ float sp[128];
    __shared__ float sm2[128];
    int g = blockIdx.x;
    int c = threadIdx.x;

    int lo = 0, hi = N_NODES;
    while (lo < hi) { int mid = (lo + hi) >> 1; if (batch[mid] < g) lo = mid + 1; else hi = mid; }
    int start = lo;
    lo = start; hi = N_NODES;
    while (lo < hi) { int mid = (lo + hi) >> 1; if (batch[mid] < g + 1) lo = mid + 1; else hi = mid; }
    int end = lo;

    float acc = 0.f;
    for (int r = start; r < end; r++) acc += __half2float(h[(size_t)r * HID + c]);
    int cnt = end - start;
    sp[c] = acc / (float)(cnt > 0 ? cnt : 1);
    __syncthreads();

    float m = 0.f;
#pragma unroll 8
    for (int k = 0; k < HID; k++) m = fmaf(sp[k], W3[k * HID + c], m);
    sm2[c] = fmaxf(m + b3[c], 0.f);
    __syncthreads();

    if (c < OUT_CH) {
        float o = 0.f;
#pragma unroll 8
        for (int k = 0; k < HID; k++) o = fmaf(sm2[k], W4[k * OUT_CH + c], o);
        out[g * OUT_CH + c] = o + b4[c];
    }
}

// ---------------- launch ------------------------------------------------------
extern "C" void kernel_launch(void* const* d_in, const int* in_sizes, int n_in,
                              void* d_out, int out_size) {
    const float* x   = (const float*)d_in[0];
    const int*   ei  = (const int*)d_in[1];
    const int*   bat = (const int*)d_in[2];
    const float* W1  = (const float*)d_in[3];
    const float* b1  = (const float*)d_in[4];
    const float* W2  = (const float*)d_in[5];
    const float* b2  = (const float*)d_in[6];
    const float* W3  = (const float*)d_in[7];
    const float* b3  = (const float*)d_in[8];
    const float* W4  = (const float*)d_in[9];
    const float* b4  = (const float*)d_in[10];
    float* out = (float*)d_out;

    __half* hs; __half* h2; int* deg; __half* wt1; __half* wt2;
    cudaGetSymbolAddress((void**)&hs,  g_hs);
    cudaGetSymbolAddress((void**)&h2,  g_h2);
    cudaGetSymbolAddress((void**)&deg, g_deg);
    cudaGetSymbolAddress((void**)&wt1, g_Wt1);
    cudaGetSymbolAddress((void**)&wt2, g_Wt2);

    const int SMG = 2 * 128 * 136 * 2;   // 69632 B
    cudaFuncSetAttribute(k_gemm_mma<false>, cudaFuncAttributeMaxDynamicSharedMemorySize, SMG);
    cudaFuncSetAttribute(k_gemm_mma<true>,  cudaFuncAttributeMaxDynamicSharedMemorySize, SMG);

    const int TB = 256;
    int nbE4 = (N_EDGES / 4 + TB - 1) / TB;
    int nbAgg = (N_NODES * 32 + TB - 1) / TB;
    int nbGemmN = (N_NODES + 127) / 128;    // 782

    cudaStream_t s2 = g_fork.s2;

    // fork at origin: W transposes independent of everything
    cudaEventRecord(g_fork.evO, 0);
    cudaStreamWaitEvent(s2, g_fork.evO, 0);
    k_wt<<<dim3(4, 4), dim3(32, 32), 0, s2>>>(W1, wt1);
    k_wt<<<dim3(4, 4), dim3(32, 32), 0, s2>>>(W2, wt2);

    // main: deg + ranks (concurrent with W transposes)
    cudaMemsetAsync(deg, 0, N_NODES * sizeof(int));
    k_count<<<nbE4, TB>>>(ei);
    cudaEventRecord(g_fork.evC, 0);

    // side: GEMM1 (epilogue scales by rsqrt(deg+1)) while main scans+scatters
    cudaStreamWaitEvent(s2, g_fork.evC, 0);
    k_gemm_mma<false><<<nbGemmN, 256, SMG, s2>>>(x, wt1, hs, N_NODES);
    cudaEventRecord(g_fork.evG1, s2);

    k_scan1<<<NB_SCAN, 1024>>>();
    k_scan3<<<NB_SCAN, 1024>>>(NB_SCAN);
    k_scatter<<<nbE4, TB>>>(ei);

    // join; everything after is serial (aggs are L2-BW-bound — no overlap wins)
    cudaStreamWaitEvent(0, g_fork.evG1, 0);

    k_agg<<<nbAgg, TB>>>((const uint4*)hs, b1, (uint4*)h2);
    k_gemm_mma<true><<<nbGemmN, 256, SMG>>>(h2, wt2, hs, N_NODES);
    k_agg<<<nbAgg, TB>>>((const uint4*)hs, b2, (uint4*)h2);
    k_head<<<N_GRAPHS, 128>>>(h2, bat, W3, b3, W4, b4, out);
}

// round 14
// speedup vs baseline: 1.1048x; 1.0094x over previous
#include <cuda_runtime.h>
#include <cuda_fp16.h>
#include <cstdint>

#define N_NODES  100000
#define N_EDGES  1600000
#define IN_CH    128
#define HID      128
#define OUT_CH   64
#define N_GRAPHS 512

static const int NB_SCAN = (N_NODES + 1023) / 1024;   // 98

// ---------------- scratch (device globals) ----------------------------------
__device__ int    g_deg[N_NODES];
__device__ int    g_incl[N_NODES];
__device__ int    g_bsum[128];
__device__ int    g_rowptr[N_NODES + 1];
__device__ int    g_rank[N_EDGES];
__device__ int    g_srcidx[N_EDGES];
__device__ float  g_dinv[N_NODES];
__device__ __half g_hs[(size_t)N_NODES * HID];     // fp16 dinv*(X@W)
__device__ __half g_h2[(size_t)N_NODES * HID];     // fp16 conv output
__device__ uint4  g_Wp1[2048];                     // frag-packed fp16 W1
__device__ uint4  g_Wp2[2048];                     // frag-packed fp16 W2

// ---------------- side stream / events (static init: in memory baseline) ----
struct ForkRes {
    cudaStream_t s2;
    cudaEvent_t  evO, evC, evG1;
    ForkRes() {
        cudaStreamCreateWithFlags(&s2, cudaStreamNonBlocking);
        cudaEventCreateWithFlags(&evO,  cudaEventDisableTiming);
        cudaEventCreateWithFlags(&evC,  cudaEventDisableTiming);
        cudaEventCreateWithFlags(&evG1, cudaEventDisableTiming);
    }
};
static ForkRes g_fork;

// ---------------- CSR build --------------------------------------------------
__global__ void k_count(const int* __restrict__ ei) {
    int t = blockIdx.x * blockDim.x + threadIdx.x;
    if (t * 4 >= N_EDGES) return;
    int4 d = ((const int4*)(ei + N_EDGES))[t];
    int4 r;
    r.x = atomicAdd(&g_deg[d.x], 1);
    r.y = atomicAdd(&g_deg[d.y], 1);
    r.z = atomicAdd(&g_deg[d.z], 1);
    r.w = atomicAdd(&g_deg[d.w], 1);
    ((int4*)g_rank)[t] = r;
}

__global__ void k_scan1() {
    __shared__ int s[1024];
    int t = threadIdx.x;
    int i = blockIdx.x * 1024 + t;
    int v = (i < N_NODES) ? g_deg[i] : 0;
    s[t] = v;
    __syncthreads();
    for (int off = 1; off < 1024; off <<= 1) {
        int a = (t >= off) ? s[t - off] : 0;
        __syncthreads();
        s[t] += a;
        __syncthreads();
    }
    if (i < N_NODES) g_incl[i] = s[t];
    if (t == 1023) g_bsum[blockIdx.x] = s[1023];
}

__global__ void k_scan3(int nb) {
    __shared__ int tmp[128];
    __shared__ int soff;
    int t = threadIdx.x;
    if (t < 128) tmp[t] = (t < (int)blockIdx.x && t < nb) ? g_bsum[t] : 0;
    __syncthreads();
    if (t == 0) {
        int s = 0;
#pragma unroll
        for (int j = 0; j < 128; j++) s += tmp[j];
        soff = s;
    }
    __syncthreads();
    int i = blockIdx.x * 1024 + t;
    if (i < N_NODES) {
        int d = g_deg[i];
        g_rowptr[i] = g_incl[i] - d + soff;
        g_dinv[i]   = rsqrtf((float)(d + 1));
    }
    if (i == 0) g_rowptr[N_NODES] = N_EDGES;
}

__global__ void k_scatter(const int* __restrict__ ei) {
    int t = blockIdx.x * blockDim.x + threadIdx.x;
    if (t * 4 >= N_EDGES) return;
    int4 s = ((const int4*)ei)[t];
    int4 d = ((const int4*)(ei + N_EDGES))[t];
    int4 r = ((const int4*)g_rank)[t];
    g_srcidx[g_rowptr[d.x] + r.x] = s.x;
    g_srcidx[g_rowptr[d.y] + r.y] = s.y;
    g_srcidx[g_rowptr[d.z] + r.z] = s.z;
    g_srcidx[g_rowptr[d.w] + r.w] = s.w;
}

// ---------------- W frag-pack to fp16 ----------------------------------------
// Wp[ks][np][lane] = uint4{ b0(nt=2np), b1(nt=2np), b0(nt=2np+1), b1(nt=2np+1) }
// matching mma.m16n8k16 .row.col B-fragment ownership for this lane.
__global__ void k_wpack(const float* __restrict__ W, uint4* __restrict__ Wp) {
    int idx = blockIdx.x * 256 + threadIdx.x;     // 0..2047
    int lane = idx & 31;
    int np = (idx >> 5) & 7;
    int ks = idx >> 8;
    int g = lane >> 2, s2 = (lane & 3) * 2;
    int kb = ks * 16;
    int n0 = np * 16 + g;                          // nt=2np  -> n = nt*8+g
    int n1 = n0 + 8;                               // nt=2np+1
    __half2 x = __floats2half2_rn(W[(kb + s2) * HID + n0], W[(kb + s2 + 1) * HID + n0]);
    __half2 y = __floats2half2_rn(W[(kb + s2 + 8) * HID + n0], W[(kb + s2 + 9) * HID + n0]);
    __half2 z = __floats2half2_rn(W[(kb + s2) * HID + n1], W[(kb + s2 + 1) * HID + n1]);
    __half2 w = __floats2half2_rn(W[(kb + s2 + 8) * HID + n1], W[(kb + s2 + 9) * HID + n1]);
    uint4 v;
    v.x = *(unsigned*)&x; v.y = *(unsigned*)&y;
    v.z = *(unsigned*)&z; v.w = *(unsigned*)&w;
    Wp[idx] = v;
}

// ---------------- tensor-core GEMM (128x128 W, K=128) -----------------------
// out[row] = fp16( rsqrtf(deg[row]+1) * (X[row] @ W) ), B frag-packed in smem.
template <bool HALF_IN>
__global__ void __launch_bounds__(256) k_gemm_mma(
        const void* __restrict__ Xv, const uint4* __restrict__ Wp,
        __half* __restrict__ out, int M) {
    constexpr int AS = 136;
    extern __shared__ __half sm[];
    __half* Asm = sm;                              // [128][AS]  (34816 B)
    uint4*  Bs  = (uint4*)(sm + 128 * AS);         // [2048]     (32768 B)
    int t = threadIdx.x;
    int rowBase = blockIdx.x * 128;

    if (HALF_IN) {
        const uint4* X = (const uint4*)Xv;
        for (int idx = t; idx < 128 * 16; idx += 256) {
            int r = idx >> 4, c8 = idx & 15;
            uint4 v = make_uint4(0u, 0u, 0u, 0u);
            int gr = rowBase + r;
            if (gr < M) v = X[(size_t)gr * 16 + c8];
            *(uint4*)&Asm[r * AS + c8 * 8] = v;
        }
    } else {
        const float4* X = (const float4*)Xv;
        for (int idx = t; idx < 128 * 32; idx += 256) {
            int r = idx >> 5, c4 = idx & 31;
            float4 v = make_float4(0.f, 0.f, 0.f, 0.f);
            int gr = rowBase + r;
            if (gr < M) v = X[(size_t)gr * 32 + c4];
            *(__half2*)&Asm[r * AS + c4 * 4]     = __floats2half2_rn(v.x, v.y);
            *(__half2*)&Asm[r * AS + c4 * 4 + 2] = __floats2half2_rn(v.z, v.w);
        }
    }
    for (int idx = t; idx < 2048; idx += 256) Bs[idx] = Wp[idx];
    __syncthreads();

    int w = t >> 5, lane = t & 31;
    int g = lane >> 2, s = lane & 3;
    int strip = w * 16;

    float acc[16][4];
#pragma unroll
    for (int nt = 0; nt < 16; nt++)
#pragma unroll
        for (int q = 0; q < 4; q++) acc[nt][q] = 0.f;

    const __half* Arow0 = &Asm[(strip + g) * AS + s * 2];
    const __half* Arow1 = Arow0 + 8 * AS;
#pragma unroll
    for (int ks = 0; ks < 8; ks++) {
        int kb = ks * 16;
        unsigned a0 = *(const unsigned*)(Arow0 + kb);
        unsigned a1 = *(const unsigned*)(Arow1 + kb);
        unsigned a2 = *(const unsigned*)(Arow0 + kb + 8);
        unsigned a3 = *(const unsigned*)(Arow1 + kb + 8);
        const uint4* Bk = Bs + ks * 256 + lane;
#pragma unroll
        for (int np = 0; np < 8; np++) {
            uint4 b = Bk[np * 32];
            asm volatile(
                "mma.sync.aligned.m16n8k16.row.col.f32.f16.f16.f32 "
                "{%0,%1,%2,%3}, {%4,%5,%6,%7}, {%8,%9}, {%0,%1,%2,%3};"
                : "+f"(acc[2*np][0]), "+f"(acc[2*np][1]), "+f"(acc[2*np][2]), "+f"(acc[2*np][3])
                : "r"(a0), "r"(a1), "r"(a2), "r"(a3), "r"(b.x), "r"(b.y));
            asm volatile(
                "mma.sync.aligned.m16n8k16.row.col.f32.f16.f16.f32 "
                "{%0,%1,%2,%3}, {%4,%5,%6,%7}, {%8,%9}, {%0,%1,%2,%3};"
                : "+f"(acc[2*np+1][0]), "+f"(acc[2*np+1][1]), "+f"(acc[2*np+1][2]), "+f"(acc[2*np+1][3])
                : "r"(a0), "r"(a1), "r"(a2), "r"(a3), "r"(b.z), "r"(b.w));
        }
    }

    int gr0 = rowBase + strip + g;
    int gr1 = gr0 + 8;
    float dv0 = (gr0 < M) ? rsqrtf((float)(g_deg[gr0] + 1)) : 0.f;
    float dv1 = (gr1 < M) ? rsqrtf((float)(g_deg[gr1] + 1)) : 0.f;
#pragma unroll
    for (int nt = 0; nt < 16; nt++) {
        int col = nt * 8 + s * 2;
        if (gr0 < M)
            *(__half2*)&out[(size_t)gr0 * HID + col] =
                __floats2half2_rn(acc[nt][0] * dv0, acc[nt][1] * dv0);
        if (gr1 < M)
            *(__half2*)&out[(size_t)gr1 * HID + col] =
                __floats2half2_rn(acc[nt][2] * dv1, acc[nt][3] * dv1);
    }
}

// ---------------- aggregation: warp per node, 2 half-warps, LDG.128 ---------
__device__ __forceinline__ void acc8(float* a, uint4 u) {
    const __half2* h = (const __half2*)&u;
#pragma unroll
    for (int j = 0; j < 4; j++) {
        float2 f = __half22float2(h[j]);
        a[2 * j]     += f.x;
        a[2 * j + 1] += f.y;
    }
}

__global__ void __launch_bounds__(256) k_agg(
        const uint4* __restrict__ hs, const float* __restrict__ bias,
        uint4* __restrict__ out) {
    int warp = (blockIdx.x * blockDim.x + threadIdx.x) >> 5;
    int lane = threadIdx.x & 31;
    if (warp >= N_NODES) return;
    int hw = lane >> 4, c = lane & 15;

    float a[8] = {0.f, 0.f, 0.f, 0.f, 0.f, 0.f, 0.f, 0.f};
    if (hw == 0) acc8(a, hs[(size_t)warp * 16 + c]);   // self loop

    int s0 = g_rowptr[warp];
    int s1 = g_rowptr[warp + 1];
    int i = s0 + hw;
    for (; i + 14 < s1; i += 16) {
        int e[8];
#pragma unroll
        for (int q = 0; q < 8; q++) e[q] = g_srcidx[i + 2 * q];
        uint4 v[8];
#pragma unroll
        for (int q = 0; q < 8; q++) v[q] = hs[(size_t)e[q] * 16 + c];
#pragma unroll
        for (int q = 0; q < 8; q++) acc8(a, v[q]);
    }
    for (; i + 6 < s1; i += 8) {
        int e0 = g_srcidx[i];
        int e1 = g_srcidx[i + 2];
        int e2 = g_srcidx[i + 4];
        int e3 = g_srcidx[i + 6];
        uint4 v0 = hs[(size_t)e0 * 16 + c];
        uint4 v1 = hs[(size_t)e1 * 16 + c];
        uint4 v2 = hs[(size_t)e2 * 16 + c];
        uint4 v3 = hs[(size_t)e3 * 16 + c];
        acc8(a, v0); acc8(a, v1); acc8(a, v2); acc8(a, v3);
    }
    for (; i < s1; i += 2) acc8(a, hs[(size_t)g_srcidx[i] * 16 + c]);

#pragma unroll
    for (int q = 0; q < 8; q++) a[q] += __shfl_down_sync(0xffffffffu, a[q], 16);

    if (hw == 0) {
        float dv = g_dinv[warp];
        float4 b0 = ((const float4*)bias)[2 * c];
        float4 b1 = ((const float4*)bias)[2 * c + 1];
        __half2 h0 = __floats2half2_rn(fmaxf(fmaf(dv, a[0], b0.x), 0.f),
                                       fmaxf(fmaf(dv, a[1], b0.y), 0.f));
        __half2 h1 = __floats2half2_rn(fmaxf(fmaf(dv, a[2], b0.z), 0.f),
                                       fmaxf(fmaf(dv, a[3], b0.w), 0.f));
        __half2 h2 = __floats2half2_rn(fmaxf(fmaf(dv, a[4], b1.x), 0.f),
                                       fmaxf(fmaf(dv, a[5], b1.y), 0.f));
        __half2 h3 = __floats2half2_rn(fmaxf(fmaf(dv, a[6], b1.z), 0.f),
                                       fmaxf(fmaf(dv, a[7], b1.w), 0.f));
        uint4 o;
        o.x = *(unsigned*)&h0; o.y = *(unsigned*)&h1;
        o.z = *(unsigned*)&h2; o.w = *(unsigned*)&h3;
        out[(size_t)warp * 16 + c] = o;
    }
}

// ---------------- fused pool + MLP head (fp32 math, exact) ------------------
__global__ void __launch_bounds__(128) k_head(
        const __half* __restrict__ h, const int* __restrict__ batch,
        const float* __restrict__ W3, const float* __restrict__ b3,
        const float* __restrict__ W4, const float* __restrict__ b4,
        float* __restrict__ out) {
    __shared__ float sp[128];
    __shared__ float sm2[128];
    int g = blockIdx.x;
    int c = threadIdx.x;

    int lo = 0, hi = N_NODES;
    while (lo < hi) { int mid = (lo + hi) >> 1; if (batch[mid] < g) lo = mid + 1; else hi = mid; }
    int start = lo;
    lo = start; hi = N_NODES;
    while (lo < hi) { int mid = (lo + hi) >> 1; if (batch[mid] < g + 1) lo = mid + 1; else hi = mid; }
    int end = lo;

    float acc = 0.f;
    for (int r = start; r < end; r++) acc += __half2float(h[(size_t)r * HID + c]);
    int cnt = end - start;
    sp[c] = acc / (float)(cnt > 0 ? cnt : 1);
    __syncthreads();

    float m = 0.f;
#pragma unroll 8
    for (int k = 0; k < HID; k++) m = fmaf(sp[k], W3[k * HID + c], m);
    sm2[c] = fmaxf(m + b3[c], 0.f);
    __syncthreads();

    if (c < OUT_CH) {
        float o = 0.f;
#pragma unroll 8
        for (int k = 0; k < HID; k++) o = fmaf(sm2[k], W4[k * OUT_CH + c], o);
        out[g * OUT_CH + c] = o + b4[c];
    }
}

// ---------------- launch ------------------------------------------------------
extern "C" void kernel_launch(void* const* d_in, const int* in_sizes, int n_in,
                              void* d_out, int out_size) {
    const float* x   = (const float*)d_in[0];
    const int*   ei  = (const int*)d_in[1];
    const int*   bat = (const int*)d_in[2];
    const float* W1  = (const float*)d_in[3];
    const float* b1  = (const float*)d_in[4];
    const float* W2  = (const float*)d_in[5];
    const float* b2  = (const float*)d_in[6];
    const float* W3  = (const float*)d_in[7];
    const float* b3  = (const float*)d_in[8];
    const float* W4  = (const float*)d_in[9];
    const float* b4  = (const float*)d_in[10];
    float* out = (float*)d_out;

    __half* hs; __half* h2; int* deg; uint4* wp1; uint4* wp2;
    cudaGetSymbolAddress((void**)&hs,  g_hs);
    cudaGetSymbolAddress((void**)&h2,  g_h2);
    cudaGetSymbolAddress((void**)&deg, g_deg);
    cudaGetSymbolAddress((void**)&wp1, g_Wp1);
    cudaGetSymbolAddress((void**)&wp2, g_Wp2);

    const int SMG = 128 * 136 * 2 + 2048 * 16;   // 34816 + 32768 = 67584 B
    cudaFuncSetAttribute(k_gemm_mma<false>, cudaFuncAttributeMaxDynamicSharedMemorySize, SMG);
    cudaFuncSetAttribute(k_gemm_mma<true>,  cudaFuncAttributeMaxDynamicSharedMemorySize, SMG);

    const int TB = 256;
    int nbE4 = (N_EDGES / 4 + TB - 1) / TB;
    int nbAgg = (N_NODES * 32 + TB - 1) / TB;
    int nbGemmN = (N_NODES + 127) / 128;    // 782

    cudaStream_t s2 = g_fork.s2;

    // fork at origin: W frag-packing independent of everything
    cudaEventRecord(g_fork.evO, 0);
    cudaStreamWaitEvent(s2, g_fork.evO, 0);
    k_wpack<<<8, 256, 0, s2>>>(W1, wp1);
    k_wpack<<<8, 256, 0, s2>>>(W2, wp2);

    // main: deg + ranks (concurrent with W packing)
    cudaMemsetAsync(deg, 0, N_NODES * sizeof(int));
    k_count<<<nbE4, TB>>>(ei);
    cudaEventRecord(g_fork.evC, 0);

    // side: GEMM1 (epilogue scales by rsqrt(deg+1)) while main scans+scatters
    cudaStreamWaitEvent(s2, g_fork.evC, 0);
    k_gemm_mma<false><<<nbGemmN, 256, SMG, s2>>>(x, wp1, hs, N_NODES);
    cudaEventRecord(g_fork.evG1, s2);

    k_scan1<<<NB_SCAN, 1024>>>();
    k_scan3<<<NB_SCAN, 1024>>>(NB_SCAN);
    k_scatter<<<nbE4, TB>>>(ei);

    // join; everything after is serial (aggs are L2-BW-bound)
    cudaStreamWaitEvent(0, g_fork.evG1, 0);

    k_agg<<<nbAgg, TB>>>((const uint4*)hs, b1, (uint4*)h2);
    k_gemm_mma<true><<<nbGemmN, 256, SMG>>>(h2, wp2, hs, N_NODES);
    k_agg<<<nbAgg, TB>>>((const uint4*)hs, b2, (uint4*)h2);
    k_head<<<N_GRAPHS, 128>>>(h2, bat, W3, b3, W4, b4, out);
}

// round 15
// speedup vs baseline: 1.1158x; 1.0099x over previous
#include <cuda_runtime.h>
#include <cuda_fp16.h>
#include <cstdint>

#define N_NODES  100000
#define N_EDGES  1600000
#define IN_CH    128
#define HID      128
#define OUT_CH   64
#define N_GRAPHS 512

static const int NB_SCAN = (N_NODES + 1023) / 1024;   // 98

// ---------------- scratch (device globals) ----------------------------------
__device__ int    g_deg[N_NODES];
__device__ int    g_incl[N_NODES];
__device__ int    g_bsum[128];
__device__ int    g_rowptr[N_NODES + 1];
__device__ int    g_rank[N_EDGES];
__device__ int    g_srcidx[N_EDGES];
__device__ float  g_dinv[N_NODES];
__device__ __half g_hs[(size_t)N_NODES * HID];     // fp16 dinv*(X@W)
__device__ __half g_h2[(size_t)N_NODES * HID];     // fp16 conv output
__device__ uint4  g_Wp1[2048];                     // frag-packed fp16 W1
__device__ uint4  g_Wp2[2048];                     // frag-packed fp16 W2

// ---------------- side stream / events (static init: in memory baseline) ----
struct ForkRes {
    cudaStream_t s2;
    cudaEvent_t  evO, evC, evG1;
    ForkRes() {
        cudaStreamCreateWithFlags(&s2, cudaStreamNonBlocking);
        cudaEventCreateWithFlags(&evO,  cudaEventDisableTiming);
        cudaEventCreateWithFlags(&evC,  cudaEventDisableTiming);
        cudaEventCreateWithFlags(&evG1, cudaEventDisableTiming);
    }
};
static ForkRes g_fork;

// ---------------- CSR build --------------------------------------------------
__global__ void k_count(const int* __restrict__ ei) {
    int t = blockIdx.x * blockDim.x + threadIdx.x;
    if (t * 4 >= N_EDGES) return;
    int4 d = ((const int4*)(ei + N_EDGES))[t];
    int4 r;
    r.x = atomicAdd(&g_deg[d.x], 1);
    r.y = atomicAdd(&g_deg[d.y], 1);
    r.z = atomicAdd(&g_deg[d.z], 1);
    r.w = atomicAdd(&g_deg[d.w], 1);
    ((int4*)g_rank)[t] = r;
}

__global__ void k_scan1() {
    __shared__ int s[1024];
    int t = threadIdx.x;
    int i = blockIdx.x * 1024 + t;
    int v = (i < N_NODES) ? g_deg[i] : 0;
    s[t] = v;
    __syncthreads();
    for (int off = 1; off < 1024; off <<= 1) {
        int a = (t >= off) ? s[t - off] : 0;
        __syncthreads();
        s[t] += a;
        __syncthreads();
    }
    if (i < N_NODES) g_incl[i] = s[t];
    if (t == 1023) g_bsum[blockIdx.x] = s[1023];
}

__global__ void k_scan3(int nb) {
    __shared__ int tmp[128];
    __shared__ int soff;
    int t = threadIdx.x;
    if (t < 128) tmp[t] = (t < (int)blockIdx.x && t < nb) ? g_bsum[t] : 0;
    __syncthreads();
    if (t == 0) {
        int s = 0;
#pragma unroll
        for (int j = 0; j < 128; j++) s += tmp[j];
        soff = s;
    }
    __syncthreads();
    int i = blockIdx.x * 1024 + t;
    if (i < N_NODES) {
        int d = g_deg[i];
        g_rowptr[i] = g_incl[i] - d + soff;
        g_dinv[i]   = rsqrtf((float)(d + 1));
    }
    if (i == 0) g_rowptr[N_NODES] = N_EDGES;
}

__global__ void k_scatter(const int* __restrict__ ei) {
    int t = blockIdx.x * blockDim.x + threadIdx.x;
    if (t * 4 >= N_EDGES) return;
    int4 s = ((const int4*)ei)[t];
    int4 d = ((const int4*)(ei + N_EDGES))[t];
    int4 r = ((const int4*)g_rank)[t];
    g_srcidx[g_rowptr[d.x] + r.x] = s.x;
    g_srcidx[g_rowptr[d.y] + r.y] = s.y;
    g_srcidx[g_rowptr[d.z] + r.z] = s.z;
    g_srcidx[g_rowptr[d.w] + r.w] = s.w;
}

// ---------------- W frag-pack (both weights in one launch) -------------------
// Wp[ks][np][lane] = uint4{ b0(nt=2np), b1(nt=2np), b0(nt=2np+1), b1(nt=2np+1) }
__global__ void k_wpack2(const float* __restrict__ W1, const float* __restrict__ W2,
                         uint4* __restrict__ Wp1, uint4* __restrict__ Wp2) {
    int blk = blockIdx.x;
    const float* W = (blk < 8) ? W1 : W2;
    uint4* Wp = (blk < 8) ? Wp1 : Wp2;
    int idx = (blk & 7) * 256 + threadIdx.x;      // 0..2047
    int lane = idx & 31;
    int np = (idx >> 5) & 7;
    int ks = idx >> 8;
    int g = lane >> 2, s2 = (lane & 3) * 2;
    int kb = ks * 16;
    int n0 = np * 16 + g;
    int n1 = n0 + 8;
    __half2 x = __floats2half2_rn(W[(kb + s2) * HID + n0], W[(kb + s2 + 1) * HID + n0]);
    __half2 y = __floats2half2_rn(W[(kb + s2 + 8) * HID + n0], W[(kb + s2 + 9) * HID + n0]);
    __half2 z = __floats2half2_rn(W[(kb + s2) * HID + n1], W[(kb + s2 + 1) * HID + n1]);
    __half2 w = __floats2half2_rn(W[(kb + s2 + 8) * HID + n1], W[(kb + s2 + 9) * HID + n1]);
    uint4 v;
    v.x = *(unsigned*)&x; v.y = *(unsigned*)&y;
    v.z = *(unsigned*)&z; v.w = *(unsigned*)&w;
    Wp[idx] = v;
}

// ---------------- tensor-core GEMM: 64 rows/CTA, split-N warps --------------
// Warp w: rows (w>>1)*16 .. +16, cols (w&1)*64 .. +64. acc = 32 regs.
template <bool HALF_IN>
__global__ void __launch_bounds__(256) k_gemm_mma(
        const void* __restrict__ Xv, const uint4* __restrict__ Wp,
        __half* __restrict__ out, int M) {
    constexpr int AS = 136;
    extern __shared__ __half sm[];
    __half* Asm = sm;                              // [64][AS]  (17408 B)
    uint4*  Bs  = (uint4*)(sm + 64 * AS);          // [2048]    (32768 B)
    int t = threadIdx.x;
    int rowBase = blockIdx.x * 64;

    if (HALF_IN) {
        const uint4* X = (const uint4*)Xv;
        for (int idx = t; idx < 64 * 16; idx += 256) {
            int r = idx >> 4, c8 = idx & 15;
            uint4 v = make_uint4(0u, 0u, 0u, 0u);
            int gr = rowBase + r;
            if (gr < M) v = X[(size_t)gr * 16 + c8];
            *(uint4*)&Asm[r * AS + c8 * 8] = v;
        }
    } else {
        const float4* X = (const float4*)Xv;
        for (int idx = t; idx < 64 * 32; idx += 256) {
            int r = idx >> 5, c4 = idx & 31;
            float4 v = make_float4(0.f, 0.f, 0.f, 0.f);
            int gr = rowBase + r;
            if (gr < M) v = X[(size_t)gr * 32 + c4];
            *(__half2*)&Asm[r * AS + c4 * 4]     = __floats2half2_rn(v.x, v.y);
            *(__half2*)&Asm[r * AS + c4 * 4 + 2] = __floats2half2_rn(v.z, v.w);
        }
    }
    for (int idx = t; idx < 2048; idx += 256) Bs[idx] = Wp[idx];
    __syncthreads();

    int w = t >> 5, lane = t & 31;
    int g = lane >> 2, s = lane & 3;
    int strip = (w >> 1) * 16;
    int npBase = (w & 1) * 4;

    float acc[8][4];
#pragma unroll
    for (int j = 0; j < 8; j++)
#pragma unroll
        for (int q = 0; q < 4; q++) acc[j][q] = 0.f;

    const __half* Arow0 = &Asm[(strip + g) * AS + s * 2];
    const __half* Arow1 = Arow0 + 8 * AS;
#pragma unroll
    for (int ks = 0; ks < 8; ks++) {
        int kb = ks * 16;
        unsigned a0 = *(const unsigned*)(Arow0 + kb);
        unsigned a1 = *(const unsigned*)(Arow1 + kb);
        unsigned a2 = *(const unsigned*)(Arow0 + kb + 8);
        unsigned a3 = *(const unsigned*)(Arow1 + kb + 8);
        const uint4* Bk = Bs + ks * 256 + npBase * 32 + lane;
#pragma unroll
        for (int np = 0; np < 4; np++) {
            uint4 b = Bk[np * 32];
            asm volatile(
                "mma.sync.aligned.m16n8k16.row.col.f32.f16.f16.f32 "
                "{%0,%1,%2,%3}, {%4,%5,%6,%7}, {%8,%9}, {%0,%1,%2,%3};"
                : "+f"(acc[2*np][0]), "+f"(acc[2*np][1]), "+f"(acc[2*np][2]), "+f"(acc[2*np][3])
                : "r"(a0), "r"(a1), "r"(a2), "r"(a3), "r"(b.x), "r"(b.y));
            asm volatile(
                "mma.sync.aligned.m16n8k16.row.col.f32.f16.f16.f32 "
                "{%0,%1,%2,%3}, {%4,%5,%6,%7}, {%8,%9}, {%0,%1,%2,%3};"
                : "+f"(acc[2*np+1][0]), "+f"(acc[2*np+1][1]), "+f"(acc[2*np+1][2]), "+f"(acc[2*np+1][3])
                : "r"(a0), "r"(a1), "r"(a2), "r"(a3), "r"(b.z), "r"(b.w));
        }
    }

    int gr0 = rowBase + strip + g;
    int gr1 = gr0 + 8;
    float dv0 = (gr0 < M) ? rsqrtf((float)(g_deg[gr0] + 1)) : 0.f;
    float dv1 = (gr1 < M) ? rsqrtf((float)(g_deg[gr1] + 1)) : 0.f;
#pragma unroll
    for (int j = 0; j < 8; j++) {
        int col = (npBase * 2 + j) * 8 + s * 2;
        if (gr0 < M)
            *(__half2*)&out[(size_t)gr0 * HID + col] =
                __floats2half2_rn(acc[j][0] * dv0, acc[j][1] * dv0);
        if (gr1 < M)
            *(__half2*)&out[(size_t)gr1 * HID + col] =
                __floats2half2_rn(acc[j][2] * dv1, acc[j][3] * dv1);
    }
}

// ---------------- aggregation: warp per node, 2 half-warps, LDG.128 ---------
__device__ __forceinline__ void acc8(float* a, uint4 u) {
    const __half2* h = (const __half2*)&u;
#pragma unroll
    for (int j = 0; j < 4; j++) {
        float2 f = __half22float2(h[j]);
        a[2 * j]     += f.x;
        a[2 * j + 1] += f.y;
    }
}

__global__ void __launch_bounds__(256) k_agg(
        const uint4* __restrict__ hs, const float* __restrict__ bias,
        uint4* __restrict__ out) {
    int warp = (blockIdx.x * blockDim.x + threadIdx.x) >> 5;
    int lane = threadIdx.x & 31;
    if (warp >= N_NODES) return;
    int hw = lane >> 4, c = lane & 15;

    float a[8] = {0.f, 0.f, 0.f, 0.f, 0.f, 0.f, 0.f, 0.f};
    if (hw == 0) acc8(a, hs[(size_t)warp * 16 + c]);   // self loop

    int s0 = g_rowptr[warp];
    int s1 = g_rowptr[warp + 1];
    int i = s0 + hw;
    for (; i + 14 < s1; i += 16) {
        int e[8];
#pragma unroll
        for (int q = 0; q < 8; q++) e[q] = g_srcidx[i + 2 * q];
        uint4 v[8];
#pragma unroll
        for (int q = 0; q < 8; q++) v[q] = hs[(size_t)e[q] * 16 + c];
#pragma unroll
        for (int q = 0; q < 8; q++) acc8(a, v[q]);
    }
    for (; i + 6 < s1; i += 8) {
        int e0 = g_srcidx[i];
        int e1 = g_srcidx[i + 2];
        int e2 = g_srcidx[i + 4];
        int e3 = g_srcidx[i + 6];
        uint4 v0 = hs[(size_t)e0 * 16 + c];
        uint4 v1 = hs[(size_t)e1 * 16 + c];
        uint4 v2 = hs[(size_t)e2 * 16 + c];
        uint4 v3 = hs[(size_t)e3 * 16 + c];
        acc8(a, v0); acc8(a, v1); acc8(a, v2); acc8(a, v3);
    }
    for (; i < s1; i += 2) acc8(a, hs[(size_t)g_srcidx[i] * 16 + c]);

#pragma unroll
    for (int q = 0; q < 8; q++) a[q] += __shfl_down_sync(0xffffffffu, a[q], 16);

    if (hw == 0) {
        float dv = g_dinv[warp];
        float4 b0 = ((const float4*)bias)[2 * c];
        float4 b1 = ((const float4*)bias)[2 * c + 1];
        __half2 h0 = __floats2half2_rn(fmaxf(fmaf(dv, a[0], b0.x), 0.f),
                                       fmaxf(fmaf(dv, a[1], b0.y), 0.f));
        __half2 h1 = __floats2half2_rn(fmaxf(fmaf(dv, a[2], b0.z), 0.f),
                                       fmaxf(fmaf(dv, a[3], b0.w), 0.f));
        __half2 h2 = __floats2half2_rn(fmaxf(fmaf(dv, a[4], b1.x), 0.f),
                                       fmaxf(fmaf(dv, a[5], b1.y), 0.f));
        __half2 h3 = __floats2half2_rn(fmaxf(fmaf(dv, a[6], b1.z), 0.f),
                                       fmaxf(fmaf(dv, a[7], b1.w), 0.f));
        uint4 o;
        o.x = *(unsigned*)&h0; o.y = *(unsigned*)&h1;
        o.z = *(unsigned*)&h2; o.w = *(unsigned*)&h3;
        out[(size_t)warp * 16 + c] = o;
    }
}

// ---------------- fused pool + MLP head (fp32 math, exact) ------------------
__global__ void __launch_bounds__(128) k_head(
        const __half* __restrict__ h, const int* __restrict__ batch,
        const float* __restrict__ W3, const float* __restrict__ b3,
        const float* __restrict__ W4, const float* __restrict__ b4,
        float* __restrict__ out) {
    __shared__ float sp[128];
    __shared__ float sm2[128];
    int g = blockIdx.x;
    int c = threadIdx.x;

    int lo = 0, hi = N_NODES;
    while (lo < hi) { int mid = (lo + hi) >> 1; if (batch[mid] < g) lo = mid + 1; else hi = mid; }
    int start = lo;
    lo = start; hi = N_NODES;
    while (lo < hi) { int mid = (lo + hi) >> 1; if (batch[mid] < g + 1) lo = mid + 1; else hi = mid; }
    int end = lo;

    float acc = 0.f;
    for (int r = start; r < end; r++) acc += __half2float(h[(size_t)r * HID + c]);
    int cnt = end - start;
    sp[c] = acc / (float)(cnt > 0 ? cnt : 1);
    __syncthreads();

    float m = 0.f;
#pragma unroll 8
    for (int k = 0; k < HID; k++) m = fmaf(sp[k], W3[k * HID + c], m);
    sm2[c] = fmaxf(m + b3[c], 0.f);
    __syncthreads();

    if (c < OUT_CH) {
        float o = 0.f;
#pragma unroll 8
        for (int k = 0; k < HID; k++) o = fmaf(sm2[k], W4[k * OUT_CH + c], o);
        out[g * OUT_CH + c] = o + b4[c];
    }
}

// ---------------- launch ------------------------------------------------------
extern "C" void kernel_launch(void* const* d_in, const int* in_sizes, int n_in,
                              void* d_out, int out_size) {
    const float* x   = (const float*)d_in[0];
    const int*   ei  = (const int*)d_in[1];
    const int*   bat = (const int*)d_in[2];
    const float* W1  = (const float*)d_in[3];
    const float* b1  = (const float*)d_in[4];
    const float* W2  = (const float*)d_in[5];
    const float* b2  = (const float*)d_in[6];
    const float* W3  = (const float*)d_in[7];
    const float* b3  = (const float*)d_in[8];
    const float* W4  = (const float*)d_in[9];
    const float* b4  = (const float*)d_in[10];
    float* out = (float*)d_out;

    __half* hs; __half* h2; int* deg; uint4* wp1; uint4* wp2;
    cudaGetSymbolAddress((void**)&hs,  g_hs);
    cudaGetSymbolAddress((void**)&h2,  g_h2);
    cudaGetSymbolAddress((void**)&deg, g_deg);
    cudaGetSymbolAddress((void**)&wp1, g_Wp1);
    cudaGetSymbolAddress((void**)&wp2, g_Wp2);

    const int SMG = 64 * 136 * 2 + 2048 * 16;   // 17408 + 32768 = 50176 B
    cudaFuncSetAttribute(k_gemm_mma<false>, cudaFuncAttributeMaxDynamicSharedMemorySize, SMG);
    cudaFuncSetAttribute(k_gemm_mma<true>,  cudaFuncAttributeMaxDynamicSharedMemorySize, SMG);

    const int TB = 256;
    int nbE4 = (N_EDGES / 4 + TB - 1) / TB;
    int nbAgg = (N_NODES * 32 + TB - 1) / TB;
    int nbGemm = (N_NODES + 63) / 64;    // 1563

    cudaStream_t s2 = g_fork.s2;

    // fork at origin: W frag-packing independent of everything
    cudaEventRecord(g_fork.evO, 0);
    cudaStreamWaitEvent(s2, g_fork.evO, 0);
    k_wpack2<<<16, 256, 0, s2>>>(W1, W2, wp1, wp2);

    // main: deg + ranks (concurrent with W packing)
    cudaMemsetAsync(deg, 0, N_NODES * sizeof(int));
    k_count<<<nbE4, TB>>>(ei);
    cudaEventRecord(g_fork.evC, 0);

    // side: GEMM1 (epilogue scales by rsqrt(deg+1)) while main scans+scatters
    cudaStreamWaitEvent(s2, g_fork.evC, 0);
    k_gemm_mma<false><<<nbGemm, 256, SMG, s2>>>(x, wp1, hs, N_NODES);
    cudaEventRecord(g_fork.evG1, s2);

    k_scan1<<<NB_SCAN, 1024>>>();
    k_scan3<<<NB_SCAN, 1024>>>(NB_SCAN);
    k_scatter<<<nbE4, TB>>>(ei);

    // join; everything after is serial (aggs are L2-BW-bound)
    cudaStreamWaitEvent(0, g_fork.evG1, 0);

    k_agg<<<nbAgg, TB>>>((const uint4*)hs, b1, (uint4*)h2);
    k_gemm_mma<true><<<nbGemm, 256, SMG>>>(h2, wp2, hs, N_NODES);
    k_agg<<<nbAgg, TB>>>((const uint4*)hs, b2, (uint4*)h2);
    k_head<<<N_GRAPHS, 128>>>(h2, bat, W3, b3, W4, b4, out);
}